// round 1
// baseline (speedup 1.0000x reference)
#include <cuda_runtime.h>
#include <cstdint>
#include <cstddef>

#define B_   128
#define T_   512
#define H_   256
#define G4_  1024
#define NCTA 128
#define HS_STRIDE 260
#define REC_SMEM (65536 + 16*HS_STRIDE*4)

// ---------------- scratch (device globals; no allocation allowed) ----------------
__device__ float g_xz[(size_t)B_ * T_ * G4_];    // 256 MB: gate pre-activations (reused per layer)
__device__ float g_hseq[(size_t)B_ * T_ * H_];   // 64 MB: per-layer hidden sequence (reused)
__device__ float g_hbuf[2][B_ * H_];             // ping-pong h state across grid
__device__ unsigned long long g_arrive = 0ULL;   // grid barrier counters (monotonic)
__device__ unsigned long long g_release = 0ULL;

// ---------------- packed f32x2 helpers (sm_103a FFMA2) ----------------
static __device__ __forceinline__ unsigned long long f2pack(float a, float b) {
    unsigned long long r;
    asm("mov.b64 %0, {%1, %2};" : "=l"(r) : "r"(__float_as_uint(a)), "r"(__float_as_uint(b)));
    return r;
}
static __device__ __forceinline__ void f2unpack(unsigned long long v, float& a, float& b) {
    unsigned int x, y;
    asm("mov.b64 {%0, %1}, %2;" : "=r"(x), "=r"(y) : "l"(v));
    a = __uint_as_float(x); b = __uint_as_float(y);
}
static __device__ __forceinline__ unsigned long long f2fma(
    unsigned long long a, unsigned long long b, unsigned long long c) {
    unsigned long long d;
    asm("fma.rn.f32x2 %0, %1, %2, %3;" : "=l"(d) : "l"(a), "l"(b), "l"(c));
    return d;
}

// ---------------- grid-wide barrier (all 128 CTAs co-resident) ----------------
static __device__ __forceinline__ void gsync(unsigned long long& phase) {
    __syncthreads();
    if (threadIdx.x == 0) {
        __threadfence();
        unsigned long long old = atomicAdd(&g_arrive, 1ULL);
        if (old == phase * NCTA + (NCTA - 1)) {
            __threadfence();
            *(volatile unsigned long long*)&g_release = phase + 1;
        } else {
            while (*(volatile unsigned long long*)&g_release <= phase) __nanosleep(32);
        }
        __threadfence();
        phase++;
    }
    __syncthreads();
}

// ---------------- tiled fp32 GEMM with bias (+ optional tanh), f32x2 FMA ----------------
// C[M,N] = A[M,256] @ Bw[256,N] + bias ; BM=128, BN=64, BK=16, 256 threads, 8x4 per thread.
template <bool TANH>
__global__ __launch_bounds__(256) void gemm_bias(
    const float* __restrict__ A, const float* __restrict__ Bw,
    const float* __restrict__ bias, float* __restrict__ C, int N)
{
    __shared__ float As[128][20];
    __shared__ float Bs[16][64];
    const int tid = threadIdx.x;
    const int m0 = blockIdx.y * 128;
    const int n0 = blockIdx.x * 64;
    const int tr = tid >> 4;   // 0..15 -> rows tr*8..tr*8+7
    const int tc = tid & 15;   // 0..15 -> cols tc*4..tc*4+3

    unsigned long long acc[8][2];
#pragma unroll
    for (int i = 0; i < 8; i++) { acc[i][0] = 0ULL; acc[i][1] = 0ULL; }

    for (int k0 = 0; k0 < 256; k0 += 16) {
#pragma unroll
        for (int s = 0; s < 2; s++) {
            int e = tid + s * 256;
            int row = e >> 2, kq = e & 3;
            float4 v = *(const float4*)&A[(size_t)(m0 + row) * 256 + k0 + kq * 4];
            *(float4*)&As[row][kq * 4] = v;
        }
        {
            int krow = tid >> 4, nq = tid & 15;
            float4 v = *(const float4*)&Bw[(size_t)(k0 + krow) * N + n0 + nq * 4];
            *(float4*)&Bs[krow][nq * 4] = v;
        }
        __syncthreads();
#pragma unroll
        for (int kk = 0; kk < 16; kk++) {
            ulonglong2 b2 = *(const ulonglong2*)&Bs[kk][tc * 4];
#pragma unroll
            for (int i = 0; i < 8; i++) {
                float a = As[tr * 8 + i][kk];
                unsigned long long aa = f2pack(a, a);
                acc[i][0] = f2fma(aa, b2.x, acc[i][0]);
                acc[i][1] = f2fma(aa, b2.y, acc[i][1]);
            }
        }
        __syncthreads();
    }

    float4 bv = *(const float4*)&bias[n0 + tc * 4];
#pragma unroll
    for (int i = 0; i < 8; i++) {
        float c0, c1, c2, c3;
        f2unpack(acc[i][0], c0, c1);
        f2unpack(acc[i][1], c2, c3);
        c0 += bv.x; c1 += bv.y; c2 += bv.z; c3 += bv.w;
        if (TANH) { c0 = tanhf(c0); c1 = tanhf(c1); c2 = tanhf(c2); c3 = tanhf(c3); }
        *(float4*)&C[(size_t)(m0 + tr * 8 + i) * N + n0 + tc * 4] = make_float4(c0, c1, c2, c3);
    }
}

// ---------------- persistent LSTM recurrence ----------------
// 128 CTAs: 8 batch-blocks (16 rows) x 16 col-blocks (16 h-cols => 64 gate-cols).
// U slice resident in smem (as f32x2 pairs: (i,f),(g,o)) for all 512 steps.
__global__ __launch_bounds__(256) void lstm_rec(
    const float* __restrict__ xz, const float* __restrict__ U, float* __restrict__ hseq)
{
    extern __shared__ unsigned char sraw[];
    ulonglong2* Us2 = (ulonglong2*)sraw;          // [256 k][16 j] -> 64 KB
    float* hs = (float*)(sraw + 65536);           // [16 rows][260] padded

    const int tid = threadIdx.x;
    const int cta = blockIdx.x;
    const int r0 = (cta >> 4) * 16;   // batch rows
    const int j0 = (cta & 15) * 16;   // h columns
    const int r = tid >> 4;           // 0..15
    const int j = tid & 15;           // 0..15

    // Load U slice once: Us2[k*16+j] = {(U[k][i_col],U[k][f_col]), (U[k][g_col],U[k][o_col])}
    for (int e = tid; e < 4096; e += 256) {
        int k = e >> 4, jj = e & 15;
        const float* up = U + (size_t)k * G4_ + j0 + jj;
        ulonglong2 v;
        v.x = f2pack(up[0], up[256]);
        v.y = f2pack(up[512], up[768]);
        Us2[e] = v;
    }

    // Zero initial h state (buffer 0), this CTA's cells
    g_hbuf[0][(r0 + r) * H_ + j0 + j] = 0.f;

    float c = 0.f;
    unsigned long long phase = 0;
    if (tid == 0) phase = *(volatile unsigned long long*)&g_release;
    gsync(phase);

    for (int t = 0; t < T_; ++t) {
        // Load h tile [16 x 256] for our batch rows (L2-coherent reads)
        const float* hb = g_hbuf[t & 1];
        const float4* src = (const float4*)(hb + (size_t)r0 * H_);
#pragma unroll
        for (int i = 0; i < 4; i++) {
            int e = tid + i * 256;
            int rr = e >> 6, cc = e & 63;
            float4 v = __ldcg(&src[(size_t)rr * 64 + cc]);
            *(float4*)&hs[rr * HS_STRIDE + cc * 4] = v;
        }
        // Prefetch this thread's 4 gate pre-activations (streaming)
        const float* xp = xz + ((size_t)(r0 + r) * T_ + t) * G4_ + j0 + j;
        float zi = __ldcs(xp);
        float zf = __ldcs(xp + 256);
        float zg = __ldcs(xp + 512);
        float zo = __ldcs(xp + 768);
        __syncthreads();

        unsigned long long accA = f2pack(zi, zf);
        unsigned long long accB = f2pack(zg, zo);
        const float* hrow = hs + r * HS_STRIDE;
        const ulonglong2* uc = Us2 + j;
#pragma unroll 8
        for (int k = 0; k < 256; k++) {
            float hv = hrow[k];
            unsigned long long hh = f2pack(hv, hv);
            ulonglong2 u = uc[(size_t)k * 16];
            accA = f2fma(hh, u.x, accA);
            accB = f2fma(hh, u.y, accB);
        }
        float azi, azf, azg, azo;
        f2unpack(accA, azi, azf);
        f2unpack(accB, azg, azo);
        float ig = 1.f / (1.f + expf(-azi));
        float fg = 1.f / (1.f + expf(-azf));
        float gg = tanhf(azg);
        float og = 1.f / (1.f + expf(-azo));
        c = fg * c + ig * gg;
        float h = og * tanhf(c);

        g_hbuf[(t + 1) & 1][(r0 + r) * H_ + j0 + j] = h;
        hseq[((size_t)(r0 + r) * T_ + t) * H_ + j0 + j] = h;
        gsync(phase);
    }
}

// ---------------- LayerNorm over last dim (256), one warp per row ----------------
__global__ __launch_bounds__(256) void ln_kernel(
    const float* __restrict__ X, const float* __restrict__ gamma,
    const float* __restrict__ beta, float* __restrict__ out)
{
    int w = threadIdx.x >> 5, lane = threadIdx.x & 31;
    size_t row = (size_t)blockIdx.x * 8 + w;
    const float* x = X + row * 256;
    float4 v0 = *(const float4*)&x[lane * 4];
    float4 v1 = *(const float4*)&x[128 + lane * 4];
    float s = v0.x + v0.y + v0.z + v0.w + v1.x + v1.y + v1.z + v1.w;
    float q = v0.x * v0.x + v0.y * v0.y + v0.z * v0.z + v0.w * v0.w
            + v1.x * v1.x + v1.y * v1.y + v1.z * v1.z + v1.w * v1.w;
#pragma unroll
    for (int o = 16; o > 0; o >>= 1) {
        s += __shfl_xor_sync(0xFFFFFFFFu, s, o);
        q += __shfl_xor_sync(0xFFFFFFFFu, q, o);
    }
    float mu = s * (1.f / 256.f);
    float var = q * (1.f / 256.f) - mu * mu;
    float rstd = rsqrtf(var + 1e-3f);
    float4 g0 = *(const float4*)&gamma[lane * 4];
    float4 g1 = *(const float4*)&gamma[128 + lane * 4];
    float4 e0 = *(const float4*)&beta[lane * 4];
    float4 e1 = *(const float4*)&beta[128 + lane * 4];
    float4 o0, o1;
    o0.x = (v0.x - mu) * rstd * g0.x + e0.x;
    o0.y = (v0.y - mu) * rstd * g0.y + e0.y;
    o0.z = (v0.z - mu) * rstd * g0.z + e0.z;
    o0.w = (v0.w - mu) * rstd * g0.w + e0.w;
    o1.x = (v1.x - mu) * rstd * g1.x + e1.x;
    o1.y = (v1.y - mu) * rstd * g1.y + e1.y;
    o1.z = (v1.z - mu) * rstd * g1.z + e1.z;
    o1.w = (v1.w - mu) * rstd * g1.w + e1.w;
    float* op = out + row * 256;
    *(float4*)&op[lane * 4] = o0;
    *(float4*)&op[128 + lane * 4] = o1;
}

// ---------------- entry point ----------------
extern "C" void kernel_launch(void* const* d_in, const int* in_sizes, int n_in,
                              void* d_out, int out_size)
{
    const float* x  = (const float*)d_in[0];
    const float* W0 = (const float*)d_in[1];
    const float* U0 = (const float*)d_in[2];
    const float* b0 = (const float*)d_in[3];
    const float* W1 = (const float*)d_in[4];
    const float* U1 = (const float*)d_in[5];
    const float* b1 = (const float*)d_in[6];
    const float* Wd = (const float*)d_in[7];
    const float* bd = (const float*)d_in[8];
    const float* ga = (const float*)d_in[9];
    const float* be = (const float*)d_in[10];
    float* out = (float*)d_out;

    float *xz, *hseq;
    cudaGetSymbolAddress((void**)&xz, g_xz);
    cudaGetSymbolAddress((void**)&hseq, g_hseq);
    cudaFuncSetAttribute(lstm_rec, cudaFuncAttributeMaxDynamicSharedMemorySize, REC_SMEM);

    // Layer 0
    gemm_bias<false><<<dim3(16, 512), 256>>>(x, W0, b0, xz, G4_);
    lstm_rec<<<NCTA, 256, REC_SMEM>>>(xz, U0, hseq);
    // Layer 1
    gemm_bias<false><<<dim3(16, 512), 256>>>(hseq, W1, b1, xz, G4_);
    lstm_rec<<<NCTA, 256, REC_SMEM>>>(xz, U1, hseq);
    // Dense + tanh (into g_xz scratch), then LayerNorm
    gemm_bias<true><<<dim3(4, 512), 256>>>(hseq, Wd, bd, xz, H_);
    ln_kernel<<<8192, 256>>>(xz, ga, be, out);
}